// round 6
// baseline (speedup 1.0000x reference)
#include <cuda_runtime.h>

// Problem-fixed sizes
static constexpr int NN = 253952;
static constexpr int EE = 4000000;
static constexpr int NG = 4096;
static constexpr int SCAN_BS = 1024;
static constexpr int MAXPART = (NN + SCAN_BS - 1) / SCAN_BS + 2;
static constexpr int DBK = 256;    // degree buckets for counting sort

// Scratch (static __device__ arrays — no allocation)
__device__ float g_bufA[(size_t)NN * 64];
__device__ float g_bufB[(size_t)NN * 64];
__device__ int   g_src[EE];
__device__ int   g_dst[EE];
__device__ int2  g_csr[EE];          // packed (src, weight-bits), grouped by dst
__device__ int   g_deg[NN];
__device__ int   g_tmp[NN];
__device__ int   g_rp[NN + 1];
__device__ int   g_cur[NN];
__device__ int   g_part[MAXPART];
__device__ int   g_batch[NN];
__device__ int   g_perm[NN];         // nodes sorted by degree
__device__ int   g_dhist[DBK];
__device__ int   g_dcur[DBK];
__device__ float g_pool[NG * 52];
__device__ int   g_flags[2];

__device__ __forceinline__ float lrelu(float v) { return v > 0.0f ? v : v * 0.01f; }

// ---------------------------------------------------------------------------
// Dtype detection (int64 little-endian high words are zero)
// ---------------------------------------------------------------------------
__global__ void k_detect(const int* __restrict__ ei_raw, const int* __restrict__ b_raw,
                         int E, int N) {
    if (blockIdx.x != 0 || threadIdx.x != 0) return;
    int acc = 0;
    for (int i = 1; i < 256; i += 2) acc |= ei_raw[E + i];
    g_flags[0] = (acc == 0) ? 1 : 0;
    int base = (N / 2) & ~1;
    int acc2 = 0;
    for (int i = 1; i < 256; i += 2) acc2 |= b_raw[base + i];
    g_flags[1] = (acc2 == 0) ? 1 : 0;
}

// ---------------------------------------------------------------------------
// Prep: convert indices, pad x [N,6]->[N,8], zero deg + degree-histogram
// ---------------------------------------------------------------------------
__global__ void k_prep(const void* __restrict__ ei_raw, const void* __restrict__ b_raw,
                       const float* __restrict__ x,
                       int* __restrict__ src, int* __restrict__ dst,
                       int* __restrict__ batch32, int* __restrict__ deg,
                       float* __restrict__ xpad, int N, int E) {
    int i = blockIdx.x * blockDim.x + threadIdx.x;
    bool ei64 = g_flags[0] != 0;
    bool b64 = g_flags[1] != 0;
    if (i < E) {
        if (ei64) {
            const long long* p = (const long long*)ei_raw;
            src[i] = (int)p[i];
            dst[i] = (int)p[(size_t)E + i];
        } else {
            const int* p = (const int*)ei_raw;
            src[i] = p[i];
            dst[i] = p[(size_t)E + i];
        }
    }
    if (i < DBK) { g_dhist[i] = 0; }
    if (i < N) {
        deg[i] = 0;
        batch32[i] = b64 ? (int)((const long long*)b_raw)[i] : ((const int*)b_raw)[i];
        const float* xr = x + (size_t)i * 6;
        float* o = xpad + (size_t)i * 8;
        o[0] = xr[0]; o[1] = xr[1]; o[2] = xr[2];
        o[3] = xr[3]; o[4] = xr[4]; o[5] = xr[5];
        o[6] = 0.0f;  o[7] = 0.0f;
    }
}

// ---------------------------------------------------------------------------
// CSR build: histogram -> 2-level exclusive scan -> fill
// ---------------------------------------------------------------------------
__global__ void k_hist(const int* __restrict__ dst, int* __restrict__ deg, int E) {
    int e = blockIdx.x * blockDim.x + threadIdx.x;
    if (e < E) atomicAdd(&deg[dst[e]], 1);
}

__global__ void k_scan1(const int* __restrict__ deg, int* __restrict__ tmp,
                        int* __restrict__ part, int N) {
    __shared__ int s[SCAN_BS];
    int i = blockIdx.x * SCAN_BS + threadIdx.x;
    int v = (i < N) ? deg[i] : 0;
    s[threadIdx.x] = v;
    __syncthreads();
    for (int off = 1; off < SCAN_BS; off <<= 1) {
        int add = (threadIdx.x >= off) ? s[threadIdx.x - off] : 0;
        __syncthreads();
        s[threadIdx.x] += add;
        __syncthreads();
    }
    if (i < N) tmp[i] = s[threadIdx.x];                 // inclusive
    if (threadIdx.x == SCAN_BS - 1) part[blockIdx.x] = s[threadIdx.x];
}

__global__ void k_scan2(int* __restrict__ part, int nb) {
    if (threadIdx.x != 0 || blockIdx.x != 0) return;
    int run = 0;
    for (int b = 0; b < nb; b++) { int v = part[b]; part[b] = run; run += v; }
}

__global__ void k_scan3(const int* __restrict__ tmp, const int* __restrict__ deg,
                        const int* __restrict__ part,
                        int* __restrict__ rp, int* __restrict__ cur, int N, int E) {
    int i = blockIdx.x * blockDim.x + threadIdx.x;
    if (i < N) {
        int excl = tmp[i] - deg[i] + part[i / SCAN_BS];
        rp[i] = excl;
        cur[i] = excl;
    }
    if (i == 0) rp[N] = E;
}

__global__ void k_fill(const int* __restrict__ src, const int* __restrict__ dst,
                       const float* __restrict__ ew,
                       int* __restrict__ cur, int2* __restrict__ csr, int E) {
    int e = blockIdx.x * blockDim.x + threadIdx.x;
    if (e >= E) return;
    int d = dst[e];
    int pos = atomicAdd(&cur[d], 1);
    csr[pos] = make_int2(src[e], __float_as_int(ew[e]));
}

// ---------------------------------------------------------------------------
// Degree counting sort: histogram (in k_prep/k_dhist) -> scan -> scatter
// ---------------------------------------------------------------------------
__global__ void k_dhist(const int* __restrict__ deg, int N) {
    int i = blockIdx.x * blockDim.x + threadIdx.x;
    if (i < N) {
        int d = deg[i]; if (d > DBK - 1) d = DBK - 1;
        atomicAdd(&g_dhist[d], 1);
    }
}

__global__ void k_dscan() {
    if (threadIdx.x != 0 || blockIdx.x != 0) return;
    int run = 0;
    for (int d = 0; d < DBK; d++) { int v = g_dhist[d]; g_dcur[d] = run; run += v; }
}

__global__ void k_dfill(const int* __restrict__ deg, int* __restrict__ perm, int N) {
    int i = blockIdx.x * blockDim.x + threadIdx.x;
    if (i < N) {
        int d = deg[i]; if (d > DBK - 1) d = DBK - 1;
        int pos = atomicAdd(&g_dcur[d], 1);
        perm[pos] = i;
    }
}

// ---------------------------------------------------------------------------
// Pull aggregation over degree-sorted nodes: thread = (sorted-node, f4-group).
// Warps see equal-degree nodes -> no trip-count divergence.
// ---------------------------------------------------------------------------
template <int STRIDE>
__global__ void k_pull(const float* __restrict__ h, const int2* __restrict__ csr,
                       const int* __restrict__ rp, const int* __restrict__ perm,
                       float* __restrict__ agg, int N) {
    constexpr int T = STRIDE / 4;
    int t = blockIdx.x * blockDim.x + threadIdx.x;
    int idx = t / T;
    int g = t % T;
    if (idx >= N) return;
    int node = __ldg(&perm[idx]);
    int e = __ldg(&rp[node]);
    int end = __ldg(&rp[node + 1]);
    float4 acc = make_float4(0.f, 0.f, 0.f, 0.f);
    float4 acc2 = make_float4(0.f, 0.f, 0.f, 0.f);
    for (; e + 1 < end; e += 2) {
        int2 p0 = __ldg(&csr[e]);
        int2 p1 = __ldg(&csr[e + 1]);
        float w0 = __int_as_float(p0.y);
        float w1 = __int_as_float(p1.y);
        float4 a = __ldg(reinterpret_cast<const float4*>(h + (size_t)p0.x * STRIDE + g * 4));
        float4 b = __ldg(reinterpret_cast<const float4*>(h + (size_t)p1.x * STRIDE + g * 4));
        acc.x += a.x * w0;  acc.y += a.y * w0;  acc.z += a.z * w0;  acc.w += a.w * w0;
        acc2.x += b.x * w1; acc2.y += b.y * w1; acc2.z += b.z * w1; acc2.w += b.w * w1;
    }
    if (e < end) {
        int2 p0 = __ldg(&csr[e]);
        float w0 = __int_as_float(p0.y);
        float4 a = __ldg(reinterpret_cast<const float4*>(h + (size_t)p0.x * STRIDE + g * 4));
        acc.x += a.x * w0; acc.y += a.y * w0; acc.z += a.z * w0; acc.w += a.w * w0;
    }
    acc.x += acc2.x; acc.y += acc2.y; acc.z += acc2.z; acc.w += acc2.w;
    *reinterpret_cast<float4*>(agg + (size_t)node * STRIDE + g * 4) = acc;
}

// ---------------------------------------------------------------------------
// Node transform: out = act(agg @ W (+b)); pads zeroed. W [IN, OUT] row-major.
// ---------------------------------------------------------------------------
template <int IN, int INS, int OUT, int OUTS, bool BIAS, bool ACT>
__global__ void k_transform(const float* __restrict__ agg,
                            const float* __restrict__ W, const float* __restrict__ b,
                            float* __restrict__ out, int N) {
    __shared__ float sW[IN * OUT];
    __shared__ float sb[OUT > 0 ? OUT : 1];
    for (int i = threadIdx.x; i < IN * OUT; i += blockDim.x) sW[i] = W[i];
    if (BIAS)
        for (int i = threadIdx.x; i < OUT; i += blockDim.x) sb[i] = b[i];
    __syncthreads();
    int n = blockIdx.x * blockDim.x + threadIdx.x;
    if (n >= N) return;
    float a[IN];
#pragma unroll
    for (int k = 0; k < IN; k++) a[k] = agg[(size_t)n * INS + k];
    float* orow = out + (size_t)n * OUTS;
    for (int of = 0; of < OUT; of++) {
        float acc = BIAS ? sb[of] : 0.0f;
#pragma unroll
        for (int k = 0; k < IN; k++) acc += a[k] * sW[k * OUT + of];
        if (ACT) acc = lrelu(acc);
        orow[of] = acc;
    }
    for (int of = OUT; of < OUTS; of++) orow[of] = 0.0f;
}

// ---------------------------------------------------------------------------
// Pool with fused layer-4 bias + double lrelu. h stride 52, cols<50.
// batch sorted -> run-length local accumulation, atomics on boundaries only.
// ---------------------------------------------------------------------------
__global__ void k_pool(const float* __restrict__ h, const int* __restrict__ batch,
                       const float* __restrict__ b4,
                       float* __restrict__ pooled, int N) {
    int g = blockIdx.y;                                   // 0..12 feature group
    int c0 = g * 4;
    float bx = (c0 + 0 < 50) ? b4[c0 + 0] : 0.f;
    float by = (c0 + 1 < 50) ? b4[c0 + 1] : 0.f;
    float bz = (c0 + 2 < 50) ? b4[c0 + 2] : 0.f;
    float bw = (c0 + 3 < 50) ? b4[c0 + 3] : 0.f;
    int chunk = blockIdx.x * blockDim.x + threadIdx.x;
    int n0 = chunk * 64;
    if (n0 >= N) return;
    int n1 = min(n0 + 64, N);
    int cur = batch[n0];
    float4 acc = make_float4(0.f, 0.f, 0.f, 0.f);
    for (int n = n0; n < n1; n++) {
        int bg = batch[n];
        if (bg != cur) {
            atomicAdd(reinterpret_cast<float4*>(pooled + (size_t)cur * 52 + c0), acc);
            acc = make_float4(0.f, 0.f, 0.f, 0.f);
            cur = bg;
        }
        float4 v = *reinterpret_cast<const float4*>(h + (size_t)n * 52 + c0);
        if (c0 + 0 < 50) acc.x += lrelu(lrelu(v.x + bx));
        if (c0 + 1 < 50) acc.y += lrelu(lrelu(v.y + by));
        if (c0 + 2 < 50) acc.z += lrelu(lrelu(v.z + bz));
        if (c0 + 3 < 50) acc.w += lrelu(lrelu(v.w + bw));
    }
    atomicAdd(reinterpret_cast<float4*>(pooled + (size_t)cur * 52 + c0), acc);
}

// ---------------------------------------------------------------------------
// Zero fill (float4)
// ---------------------------------------------------------------------------
__global__ void k_zero(float4* __restrict__ p, int n4) {
    int i = blockIdx.x * blockDim.x + threadIdx.x;
    if (i < n4) p[i] = make_float4(0.f, 0.f, 0.f, 0.f);
}

// ---------------------------------------------------------------------------
// MLP head: [G,50] -> 30 -> 20 -> 2
// ---------------------------------------------------------------------------
__global__ void k_fc(const float* __restrict__ pooled,
                     const float* __restrict__ W1, const float* __restrict__ b1,
                     const float* __restrict__ W2, const float* __restrict__ b2,
                     const float* __restrict__ W3, const float* __restrict__ b3,
                     float* __restrict__ out) {
    __shared__ float s1[50 * 30], s2[30 * 20], s3[20 * 2];
    __shared__ float t1[30], t2[20], t3[2];
    for (int i = threadIdx.x; i < 50 * 30; i += blockDim.x) s1[i] = W1[i];
    for (int i = threadIdx.x; i < 30 * 20; i += blockDim.x) s2[i] = W2[i];
    for (int i = threadIdx.x; i < 20 * 2; i += blockDim.x) s3[i] = W3[i];
    if (threadIdx.x < 30) t1[threadIdx.x] = b1[threadIdx.x];
    if (threadIdx.x < 20) t2[threadIdx.x] = b2[threadIdx.x];
    if (threadIdx.x < 2) t3[threadIdx.x] = b3[threadIdx.x];
    __syncthreads();
    int gi = blockIdx.x * blockDim.x + threadIdx.x;
    if (gi >= NG) return;
    float p[50];
#pragma unroll
    for (int k = 0; k < 50; k++) p[k] = pooled[(size_t)gi * 52 + k];
    float a1[30];
    for (int of = 0; of < 30; of++) {
        float acc = t1[of];
#pragma unroll
        for (int k = 0; k < 50; k++) acc += p[k] * s1[k * 30 + of];
        a1[of] = lrelu(acc);
    }
    float a2[20];
    for (int of = 0; of < 20; of++) {
        float acc = t2[of];
#pragma unroll
        for (int k = 0; k < 30; k++) acc += a1[k] * s2[k * 20 + of];
        a2[of] = lrelu(acc);
    }
#pragma unroll
    for (int of = 0; of < 2; of++) {
        float acc = t3[of];
#pragma unroll
        for (int k = 0; k < 20; k++) acc += a2[k] * s3[k * 2 + of];
        out[(size_t)gi * 2 + of] = lrelu(acc);
    }
}

// ---------------------------------------------------------------------------
extern "C" void kernel_launch(void* const* d_in, const int* in_sizes, int n_in,
                              void* d_out, int out_size) {
    const float* x     = (const float*)d_in[0];
    const void*  ei    = d_in[1];
    const float* ew    = (const float*)d_in[2];
    const void*  batch = d_in[3];
    const float* W1 = (const float*)d_in[4];  const float* b1 = (const float*)d_in[5];
    const float* W2 = (const float*)d_in[6];  const float* b2 = (const float*)d_in[7];
    const float* W3 = (const float*)d_in[8];  const float* b3 = (const float*)d_in[9];
    const float* W4 = (const float*)d_in[10]; const float* b4 = (const float*)d_in[11];
    const float* Wf1 = (const float*)d_in[12]; const float* bf1 = (const float*)d_in[13];
    const float* Wf2 = (const float*)d_in[14]; const float* bf2 = (const float*)d_in[15];
    const float* Wf3 = (const float*)d_in[16]; const float* bf3 = (const float*)d_in[17];
    float* out = (float*)d_out;

    int N = in_sizes[0] / 6;
    int E = in_sizes[2];

    float *bufA, *bufB, *pool;
    int *src, *dst, *batch32, *deg, *tmp, *rp, *cur, *part, *perm;
    int2* csr;
    cudaGetSymbolAddress((void**)&bufA, g_bufA);
    cudaGetSymbolAddress((void**)&bufB, g_bufB);
    cudaGetSymbolAddress((void**)&pool, g_pool);
    cudaGetSymbolAddress((void**)&src, g_src);
    cudaGetSymbolAddress((void**)&dst, g_dst);
    cudaGetSymbolAddress((void**)&batch32, g_batch);
    cudaGetSymbolAddress((void**)&deg, g_deg);
    cudaGetSymbolAddress((void**)&tmp, g_tmp);
    cudaGetSymbolAddress((void**)&rp, g_rp);
    cudaGetSymbolAddress((void**)&cur, g_cur);
    cudaGetSymbolAddress((void**)&part, g_part);
    cudaGetSymbolAddress((void**)&perm, g_perm);
    cudaGetSymbolAddress((void**)&csr, g_csr);

    const int BT = 256;
    int nb = (N + SCAN_BS - 1) / SCAN_BS;

    k_detect<<<1, 32>>>((const int*)ei, (const int*)batch, E, N);
    int mx = E > N ? E : N;
    k_prep<<<(mx + BT - 1) / BT, BT>>>(ei, batch, x, src, dst, batch32, deg, bufB, N, E);

    // CSR build
    k_hist<<<(E + BT - 1) / BT, BT>>>(dst, deg, E);
    k_scan1<<<nb, SCAN_BS>>>(deg, tmp, part, N);
    k_scan2<<<1, 32>>>(part, nb);
    k_scan3<<<(N + BT - 1) / BT, BT>>>(tmp, deg, part, rp, cur, N, E);
    k_fill<<<(E + BT - 1) / BT, BT>>>(src, dst, ew, cur, csr, E);

    // Degree counting sort -> perm
    k_dhist<<<(N + BT - 1) / BT, BT>>>(deg, N);
    k_dscan<<<1, 32>>>();
    k_dfill<<<(N + BT - 1) / BT, BT>>>(deg, perm, N);

    // ---- Layer 1: pull dim8, transform 6->16
    k_pull<8><<<((N * 2) + BT - 1) / BT, BT>>>(bufB, csr, rp, perm, bufA, N);
    k_transform<6, 8, 16, 16, true, true><<<(N + 127) / 128, 128>>>(bufA, W1, b1, bufB, N);
    // ---- Layer 2: pull dim16, transform 16->32
    k_pull<16><<<((N * 4) + BT - 1) / BT, BT>>>(bufB, csr, rp, perm, bufA, N);
    k_transform<16, 16, 32, 32, true, true><<<(N + 127) / 128, 128>>>(bufA, W2, b2, bufB, N);
    // ---- Layer 3: pull dim32, transform 32->64
    k_pull<32><<<((N * 8) + BT - 1) / BT, BT>>>(bufB, csr, rp, perm, bufA, N);
    k_transform<32, 32, 64, 64, true, true><<<(N + 127) / 128, 128>>>(bufA, W3, b3, bufB, N);
    // ---- Layer 4: pre-transform 64->50 (linear, pad 52), pull dim52
    k_transform<64, 64, 50, 52, false, false><<<(N + 127) / 128, 128>>>(bufB, W4, nullptr, bufA, N);
    k_pull<52><<<(((long long)N * 13 + BT - 1) / BT), BT>>>(bufA, csr, rp, perm, bufB, N);

    // ---- Pool (fused bias + double lrelu), reads stride 52
    {
        int n4 = NG * 52 / 4;
        k_zero<<<(n4 + BT - 1) / BT, BT>>>((float4*)pool, n4);
        int chunks = (N + 63) / 64;
        dim3 grid((chunks + 127) / 128, 13);
        k_pool<<<grid, 128>>>(bufB, batch32, b4, pool, N);
    }
    // ---- MLP head
    k_fc<<<(NG + BT - 1) / BT, BT>>>(pool, Wf1, bf1, Wf2, bf2, Wf3, bf3, out);
}

// round 8
// speedup vs baseline: 1.0649x; 1.0649x over previous
#include <cuda_runtime.h>

// Problem-fixed sizes
static constexpr int NN = 253952;
static constexpr int EE = 4000000;
static constexpr int NG = 4096;
static constexpr int SCAN_BS = 1024;
static constexpr int MAXPART = (NN + SCAN_BS - 1) / SCAN_BS + 2;

// Scratch (static __device__ arrays — no allocation)
__device__ float g_bufA[(size_t)NN * 64];
__device__ float g_bufB[(size_t)NN * 64];
__device__ int   g_src[EE];
__device__ int   g_dst[EE];
__device__ int2  g_csr[EE];          // packed (src, weight-bits), grouped by dst
__device__ int   g_deg[NN];
__device__ int   g_tmp[NN];
__device__ int   g_rp[NN + 1];
__device__ int   g_cur[NN];
__device__ int   g_part[MAXPART];
__device__ int   g_batch[NN];
__device__ float g_pool[NG * 52];
__device__ int   g_flags[2];

__device__ __forceinline__ float lrelu(float v) { return v > 0.0f ? v : v * 0.01f; }

// ---------------------------------------------------------------------------
// Dtype detection (int64 little-endian high words are zero)
// ---------------------------------------------------------------------------
__global__ void k_detect(const int* __restrict__ ei_raw, const int* __restrict__ b_raw,
                         int E, int N) {
    if (blockIdx.x != 0 || threadIdx.x != 0) return;
    int acc = 0;
    for (int i = 1; i < 256; i += 2) acc |= ei_raw[E + i];
    g_flags[0] = (acc == 0) ? 1 : 0;
    int base = (N / 2) & ~1;
    int acc2 = 0;
    for (int i = 1; i < 256; i += 2) acc2 |= b_raw[base + i];
    g_flags[1] = (acc2 == 0) ? 1 : 0;
}

// ---------------------------------------------------------------------------
// Prep: convert indices, pad x [N,6]->[N,8], zero deg
// ---------------------------------------------------------------------------
__global__ void k_prep(const void* __restrict__ ei_raw, const void* __restrict__ b_raw,
                       const float* __restrict__ x,
                       int* __restrict__ src, int* __restrict__ dst,
                       int* __restrict__ batch32, int* __restrict__ deg,
                       float* __restrict__ xpad, int N, int E) {
    int i = blockIdx.x * blockDim.x + threadIdx.x;
    bool ei64 = g_flags[0] != 0;
    bool b64 = g_flags[1] != 0;
    if (i < E) {
        if (ei64) {
            const long long* p = (const long long*)ei_raw;
            src[i] = (int)p[i];
            dst[i] = (int)p[(size_t)E + i];
        } else {
            const int* p = (const int*)ei_raw;
            src[i] = p[i];
            dst[i] = p[(size_t)E + i];
        }
    }
    if (i < N) {
        deg[i] = 0;
        batch32[i] = b64 ? (int)((const long long*)b_raw)[i] : ((const int*)b_raw)[i];
        const float* xr = x + (size_t)i * 6;
        float* o = xpad + (size_t)i * 8;
        o[0] = xr[0]; o[1] = xr[1]; o[2] = xr[2];
        o[3] = xr[3]; o[4] = xr[4]; o[5] = xr[5];
        o[6] = 0.0f;  o[7] = 0.0f;
    }
}

// ---------------------------------------------------------------------------
// CSR build: histogram -> 2-level exclusive scan -> fill
// ---------------------------------------------------------------------------
__global__ void k_hist(const int* __restrict__ dst, int* __restrict__ deg, int E) {
    int e = blockIdx.x * blockDim.x + threadIdx.x;
    if (e < E) atomicAdd(&deg[dst[e]], 1);
}

__global__ void k_scan1(const int* __restrict__ deg, int* __restrict__ tmp,
                        int* __restrict__ part, int N) {
    __shared__ int s[SCAN_BS];
    int i = blockIdx.x * SCAN_BS + threadIdx.x;
    int v = (i < N) ? deg[i] : 0;
    s[threadIdx.x] = v;
    __syncthreads();
    for (int off = 1; off < SCAN_BS; off <<= 1) {
        int add = (threadIdx.x >= off) ? s[threadIdx.x - off] : 0;
        __syncthreads();
        s[threadIdx.x] += add;
        __syncthreads();
    }
    if (i < N) tmp[i] = s[threadIdx.x];                 // inclusive
    if (threadIdx.x == SCAN_BS - 1) part[blockIdx.x] = s[threadIdx.x];
}

__global__ void k_scan2(int* __restrict__ part, int nb) {
    if (threadIdx.x != 0 || blockIdx.x != 0) return;
    int run = 0;
    for (int b = 0; b < nb; b++) { int v = part[b]; part[b] = run; run += v; }
}

__global__ void k_scan3(const int* __restrict__ tmp, const int* __restrict__ deg,
                        const int* __restrict__ part,
                        int* __restrict__ rp, int* __restrict__ cur, int N, int E) {
    int i = blockIdx.x * blockDim.x + threadIdx.x;
    if (i < N) {
        int excl = tmp[i] - deg[i] + part[i / SCAN_BS];
        rp[i] = excl;
        cur[i] = excl;
    }
    if (i == 0) rp[N] = E;
}

__global__ void k_fill(const int* __restrict__ src, const int* __restrict__ dst,
                       const float* __restrict__ ew,
                       int* __restrict__ cur, int2* __restrict__ csr, int E) {
    int e = blockIdx.x * blockDim.x + threadIdx.x;
    if (e >= E) return;
    int d = dst[e];
    int pos = atomicAdd(&cur[d], 1);
    csr[pos] = make_int2(src[e], __float_as_int(ew[e]));
}

// ---------------------------------------------------------------------------
// Pull aggregation, 32B (8 floats = full L2 sector) per thread per edge.
// thread = (node, 8-float group); T = STRIDE/8 threads per node, natural order.
// Dual accumulators over a 2-edge unrolled loop: 4 gathers in flight/thread.
// ---------------------------------------------------------------------------
template <int STRIDE>
__global__ void k_pull8(const float* __restrict__ h, const int2* __restrict__ csr,
                        const int* __restrict__ rp, float* __restrict__ agg, int N) {
    constexpr int T = STRIDE / 8;
    int t = blockIdx.x * blockDim.x + threadIdx.x;
    int node = t / T;
    int g = t % T;
    if (node >= N) return;
    int e = __ldg(&rp[node]);
    int end = __ldg(&rp[node + 1]);
    const float* hp = h + g * 8;
    float4 a0 = make_float4(0.f, 0.f, 0.f, 0.f);
    float4 a1 = make_float4(0.f, 0.f, 0.f, 0.f);
    float4 c0 = make_float4(0.f, 0.f, 0.f, 0.f);
    float4 c1 = make_float4(0.f, 0.f, 0.f, 0.f);
    for (; e + 1 < end; e += 2) {
        int2 p0 = __ldg(&csr[e]);
        int2 p1 = __ldg(&csr[e + 1]);
        float w0 = __int_as_float(p0.y);
        float w1 = __int_as_float(p1.y);
        const float4* r0 = reinterpret_cast<const float4*>(hp + (size_t)p0.x * STRIDE);
        const float4* r1 = reinterpret_cast<const float4*>(hp + (size_t)p1.x * STRIDE);
        float4 x0 = __ldg(r0);
        float4 x1 = __ldg(r0 + 1);
        float4 y0 = __ldg(r1);
        float4 y1 = __ldg(r1 + 1);
        a0.x += x0.x * w0; a0.y += x0.y * w0; a0.z += x0.z * w0; a0.w += x0.w * w0;
        a1.x += x1.x * w0; a1.y += x1.y * w0; a1.z += x1.z * w0; a1.w += x1.w * w0;
        c0.x += y0.x * w1; c0.y += y0.y * w1; c0.z += y0.z * w1; c0.w += y0.w * w1;
        c1.x += y1.x * w1; c1.y += y1.y * w1; c1.z += y1.z * w1; c1.w += y1.w * w1;
    }
    if (e < end) {
        int2 p0 = __ldg(&csr[e]);
        float w0 = __int_as_float(p0.y);
        const float4* r0 = reinterpret_cast<const float4*>(hp + (size_t)p0.x * STRIDE);
        float4 x0 = __ldg(r0);
        float4 x1 = __ldg(r0 + 1);
        a0.x += x0.x * w0; a0.y += x0.y * w0; a0.z += x0.z * w0; a0.w += x0.w * w0;
        a1.x += x1.x * w0; a1.y += x1.y * w0; a1.z += x1.z * w0; a1.w += x1.w * w0;
    }
    a0.x += c0.x; a0.y += c0.y; a0.z += c0.z; a0.w += c0.w;
    a1.x += c1.x; a1.y += c1.y; a1.z += c1.z; a1.w += c1.w;
    float4* o = reinterpret_cast<float4*>(agg + (size_t)node * STRIDE + g * 8);
    o[0] = a0;
    o[1] = a1;
}

// ---------------------------------------------------------------------------
// Node transform: out = act(agg @ W (+b)); pads zeroed. W [IN, OUT] row-major.
// ---------------------------------------------------------------------------
template <int IN, int INS, int OUT, int OUTS, bool BIAS, bool ACT>
__global__ void k_transform(const float* __restrict__ agg,
                            const float* __restrict__ W, const float* __restrict__ b,
                            float* __restrict__ out, int N) {
    __shared__ float sW[IN * OUT];
    __shared__ float sb[OUT > 0 ? OUT : 1];
    for (int i = threadIdx.x; i < IN * OUT; i += blockDim.x) sW[i] = W[i];
    if (BIAS)
        for (int i = threadIdx.x; i < OUT; i += blockDim.x) sb[i] = b[i];
    __syncthreads();
    int n = blockIdx.x * blockDim.x + threadIdx.x;
    if (n >= N) return;
    float a[IN];
#pragma unroll
    for (int k = 0; k < IN; k++) a[k] = agg[(size_t)n * INS + k];
    float* orow = out + (size_t)n * OUTS;
    for (int of = 0; of < OUT; of++) {
        float acc = BIAS ? sb[of] : 0.0f;
#pragma unroll
        for (int k = 0; k < IN; k++) acc += a[k] * sW[k * OUT + of];
        if (ACT) acc = lrelu(acc);
        orow[of] = acc;
    }
    for (int of = OUT; of < OUTS; of++) orow[of] = 0.0f;
}

// ---------------------------------------------------------------------------
// Pool with fused layer-4 bias + double lrelu. h stride 56 (padded), cols<50.
// batch sorted -> run-length local accumulation, atomics on boundaries only.
// ---------------------------------------------------------------------------
__global__ void k_pool(const float* __restrict__ h, const int* __restrict__ batch,
                       const float* __restrict__ b4,
                       float* __restrict__ pooled, int N) {
    int g = blockIdx.y;                                   // 0..12 feature group
    int c0 = g * 4;
    float bx = (c0 + 0 < 50) ? b4[c0 + 0] : 0.f;
    float by = (c0 + 1 < 50) ? b4[c0 + 1] : 0.f;
    float bz = (c0 + 2 < 50) ? b4[c0 + 2] : 0.f;
    float bw = (c0 + 3 < 50) ? b4[c0 + 3] : 0.f;
    int chunk = blockIdx.x * blockDim.x + threadIdx.x;
    int n0 = chunk * 64;
    if (n0 >= N) return;
    int n1 = min(n0 + 64, N);
    int cur = batch[n0];
    float4 acc = make_float4(0.f, 0.f, 0.f, 0.f);
    for (int n = n0; n < n1; n++) {
        int bg = batch[n];
        if (bg != cur) {
            atomicAdd(reinterpret_cast<float4*>(pooled + (size_t)cur * 52 + c0), acc);
            acc = make_float4(0.f, 0.f, 0.f, 0.f);
            cur = bg;
        }
        float4 v = *reinterpret_cast<const float4*>(h + (size_t)n * 56 + c0);
        if (c0 + 0 < 50) acc.x += lrelu(lrelu(v.x + bx));
        if (c0 + 1 < 50) acc.y += lrelu(lrelu(v.y + by));
        if (c0 + 2 < 50) acc.z += lrelu(lrelu(v.z + bz));
        if (c0 + 3 < 50) acc.w += lrelu(lrelu(v.w + bw));
    }
    atomicAdd(reinterpret_cast<float4*>(pooled + (size_t)cur * 52 + c0), acc);
}

// ---------------------------------------------------------------------------
// Zero fill (float4)
// ---------------------------------------------------------------------------
__global__ void k_zero(float4* __restrict__ p, int n4) {
    int i = blockIdx.x * blockDim.x + threadIdx.x;
    if (i < n4) p[i] = make_float4(0.f, 0.f, 0.f, 0.f);
}

// ---------------------------------------------------------------------------
// MLP head: [G,50] -> 30 -> 20 -> 2
// ---------------------------------------------------------------------------
__global__ void k_fc(const float* __restrict__ pooled,
                     const float* __restrict__ W1, const float* __restrict__ b1,
                     const float* __restrict__ W2, const float* __restrict__ b2,
                     const float* __restrict__ W3, const float* __restrict__ b3,
                     float* __restrict__ out) {
    __shared__ float s1[50 * 30], s2[30 * 20], s3[20 * 2];
    __shared__ float t1[30], t2[20], t3[2];
    for (int i = threadIdx.x; i < 50 * 30; i += blockDim.x) s1[i] = W1[i];
    for (int i = threadIdx.x; i < 30 * 20; i += blockDim.x) s2[i] = W2[i];
    for (int i = threadIdx.x; i < 20 * 2; i += blockDim.x) s3[i] = W3[i];
    if (threadIdx.x < 30) t1[threadIdx.x] = b1[threadIdx.x];
    if (threadIdx.x < 20) t2[threadIdx.x] = b2[threadIdx.x];
    if (threadIdx.x < 2) t3[threadIdx.x] = b3[threadIdx.x];
    __syncthreads();
    int gi = blockIdx.x * blockDim.x + threadIdx.x;
    if (gi >= NG) return;
    float p[50];
#pragma unroll
    for (int k = 0; k < 50; k++) p[k] = pooled[(size_t)gi * 52 + k];
    float a1[30];
    for (int of = 0; of < 30; of++) {
        float acc = t1[of];
#pragma unroll
        for (int k = 0; k < 50; k++) acc += p[k] * s1[k * 30 + of];
        a1[of] = lrelu(acc);
    }
    float a2[20];
    for (int of = 0; of < 20; of++) {
        float acc = t2[of];
#pragma unroll
        for (int k = 0; k < 30; k++) acc += a1[k] * s2[k * 20 + of];
        a2[of] = lrelu(acc);
    }
#pragma unroll
    for (int of = 0; of < 2; of++) {
        float acc = t3[of];
#pragma unroll
        for (int k = 0; k < 20; k++) acc += a2[k] * s3[k * 2 + of];
        out[(size_t)gi * 2 + of] = lrelu(acc);
    }
}

// ---------------------------------------------------------------------------
extern "C" void kernel_launch(void* const* d_in, const int* in_sizes, int n_in,
                              void* d_out, int out_size) {
    const float* x     = (const float*)d_in[0];
    const void*  ei    = d_in[1];
    const float* ew    = (const float*)d_in[2];
    const void*  batch = d_in[3];
    const float* W1 = (const float*)d_in[4];  const float* b1 = (const float*)d_in[5];
    const float* W2 = (const float*)d_in[6];  const float* b2 = (const float*)d_in[7];
    const float* W3 = (const float*)d_in[8];  const float* b3 = (const float*)d_in[9];
    const float* W4 = (const float*)d_in[10]; const float* b4 = (const float*)d_in[11];
    const float* Wf1 = (const float*)d_in[12]; const float* bf1 = (const float*)d_in[13];
    const float* Wf2 = (const float*)d_in[14]; const float* bf2 = (const float*)d_in[15];
    const float* Wf3 = (const float*)d_in[16]; const float* bf3 = (const float*)d_in[17];
    float* out = (float*)d_out;

    int N = in_sizes[0] / 6;
    int E = in_sizes[2];

    float *bufA, *bufB, *pool;
    int *src, *dst, *batch32, *deg, *tmp, *rp, *cur, *part;
    int2* csr;
    cudaGetSymbolAddress((void**)&bufA, g_bufA);
    cudaGetSymbolAddress((void**)&bufB, g_bufB);
    cudaGetSymbolAddress((void**)&pool, g_pool);
    cudaGetSymbolAddress((void**)&src, g_src);
    cudaGetSymbolAddress((void**)&dst, g_dst);
    cudaGetSymbolAddress((void**)&batch32, g_batch);
    cudaGetSymbolAddress((void**)&deg, g_deg);
    cudaGetSymbolAddress((void**)&tmp, g_tmp);
    cudaGetSymbolAddress((void**)&rp, g_rp);
    cudaGetSymbolAddress((void**)&cur, g_cur);
    cudaGetSymbolAddress((void**)&part, g_part);
    cudaGetSymbolAddress((void**)&csr, g_csr);

    const int BT = 256;
    int nb = (N + SCAN_BS - 1) / SCAN_BS;

    k_detect<<<1, 32>>>((const int*)ei, (const int*)batch, E, N);
    int mx = E > N ? E : N;
    k_prep<<<(mx + BT - 1) / BT, BT>>>(ei, batch, x, src, dst, batch32, deg, bufB, N, E);

    // CSR build
    k_hist<<<(E + BT - 1) / BT, BT>>>(dst, deg, E);
    k_scan1<<<nb, SCAN_BS>>>(deg, tmp, part, N);
    k_scan2<<<1, 32>>>(part, nb);
    k_scan3<<<(N + BT - 1) / BT, BT>>>(tmp, deg, part, rp, cur, N, E);
    k_fill<<<(E + BT - 1) / BT, BT>>>(src, dst, ew, cur, csr, E);

    // ---- Layer 1: pull dim8 (T=1), transform 6->16
    k_pull8<8><<<(N + BT - 1) / BT, BT>>>(bufB, csr, rp, bufA, N);
    k_transform<6, 8, 16, 16, true, true><<<(N + 127) / 128, 128>>>(bufA, W1, b1, bufB, N);
    // ---- Layer 2: pull dim16 (T=2), transform 16->32
    k_pull8<16><<<((N * 2) + BT - 1) / BT, BT>>>(bufB, csr, rp, bufA, N);
    k_transform<16, 16, 32, 32, true, true><<<(N + 127) / 128, 128>>>(bufA, W2, b2, bufB, N);
    // ---- Layer 3: pull dim32 (T=4), transform 32->64
    k_pull8<32><<<((N * 4) + BT - 1) / BT, BT>>>(bufB, csr, rp, bufA, N);
    k_transform<32, 32, 64, 64, true, true><<<(N + 127) / 128, 128>>>(bufA, W3, b3, bufB, N);
    // ---- Layer 4: pre-transform 64->50 (linear, pad to 56), pull dim56 (T=7)
    k_transform<64, 64, 50, 56, false, false><<<(N + 127) / 128, 128>>>(bufB, W4, nullptr, bufA, N);
    k_pull8<56><<<(unsigned)(((long long)N * 7 + BT - 1) / BT), BT>>>(bufA, csr, rp, bufB, N);

    // ---- Pool (fused bias + double lrelu), reads stride 56
    {
        int n4 = NG * 52 / 4;
        k_zero<<<(n4 + BT - 1) / BT, BT>>>((float4*)pool, n4);
        int chunks = (N + 63) / 64;
        dim3 grid((chunks + 127) / 128, 13);
        k_pool<<<grid, 128>>>(bufB, batch32, b4, pool, N);
    }
    // ---- MLP head
    k_fc<<<(NG + BT - 1) / BT, BT>>>(pool, Wf1, bf1, Wf2, bf2, Wf3, bf3, out);
}

// round 9
// speedup vs baseline: 1.1041x; 1.0367x over previous
#include <cuda_runtime.h>
#include <cuda_fp16.h>

// Problem-fixed sizes
static constexpr int NN = 253952;
static constexpr int EE = 4000000;
static constexpr int NG = 4096;
static constexpr int SCAN_BS = 1024;
static constexpr int MAXPART = (NN + SCAN_BS - 1) / SCAN_BS + 2;

// Scratch (static __device__ arrays — no allocation)
__device__ float g_bufA[(size_t)NN * 64];   // fp32 agg buffers
__device__ float g_bufB[(size_t)NN * 64];
__device__ __half g_h16[(size_t)NN * 64];   // fp16 node features (messages)
__device__ int   g_src[EE];
__device__ int   g_dst[EE];
__device__ int2  g_csr[EE];          // packed (src, weight-bits), grouped by dst
__device__ int   g_deg[NN];
__device__ int   g_tmp[NN];
__device__ int   g_rp[NN + 1];
__device__ int   g_cur[NN];
__device__ int   g_part[MAXPART];
__device__ int   g_batch[NN];
__device__ float g_pool[NG * 52];
__device__ int   g_flags[2];

__device__ __forceinline__ float lrelu(float v) { return v > 0.0f ? v : v * 0.01f; }

// ---------------------------------------------------------------------------
// Dtype detection (int64 little-endian high words are zero)
// ---------------------------------------------------------------------------
__global__ void k_detect(const int* __restrict__ ei_raw, const int* __restrict__ b_raw,
                         int E, int N) {
    if (blockIdx.x != 0 || threadIdx.x != 0) return;
    int acc = 0;
    for (int i = 1; i < 256; i += 2) acc |= ei_raw[E + i];
    g_flags[0] = (acc == 0) ? 1 : 0;
    int base = (N / 2) & ~1;
    int acc2 = 0;
    for (int i = 1; i < 256; i += 2) acc2 |= b_raw[base + i];
    g_flags[1] = (acc2 == 0) ? 1 : 0;
}

// ---------------------------------------------------------------------------
// Prep: convert indices, pad x [N,6]->[N,8] fp16, zero deg
// ---------------------------------------------------------------------------
__global__ void k_prep(const void* __restrict__ ei_raw, const void* __restrict__ b_raw,
                       const float* __restrict__ x,
                       int* __restrict__ src, int* __restrict__ dst,
                       int* __restrict__ batch32, int* __restrict__ deg,
                       __half* __restrict__ xpad, int N, int E) {
    int i = blockIdx.x * blockDim.x + threadIdx.x;
    bool ei64 = g_flags[0] != 0;
    bool b64 = g_flags[1] != 0;
    if (i < E) {
        if (ei64) {
            const long long* p = (const long long*)ei_raw;
            src[i] = (int)p[i];
            dst[i] = (int)p[(size_t)E + i];
        } else {
            const int* p = (const int*)ei_raw;
            src[i] = p[i];
            dst[i] = p[(size_t)E + i];
        }
    }
    if (i < N) {
        deg[i] = 0;
        batch32[i] = b64 ? (int)((const long long*)b_raw)[i] : ((const int*)b_raw)[i];
        const float* xr = x + (size_t)i * 6;
        __half* o = xpad + (size_t)i * 8;
        o[0] = __float2half(xr[0]); o[1] = __float2half(xr[1]);
        o[2] = __float2half(xr[2]); o[3] = __float2half(xr[3]);
        o[4] = __float2half(xr[4]); o[5] = __float2half(xr[5]);
        o[6] = __float2half(0.f);   o[7] = __float2half(0.f);
    }
}

// ---------------------------------------------------------------------------
// CSR build: histogram -> 2-level exclusive scan -> fill
// ---------------------------------------------------------------------------
__global__ void k_hist(const int* __restrict__ dst, int* __restrict__ deg, int E) {
    int e = blockIdx.x * blockDim.x + threadIdx.x;
    if (e < E) atomicAdd(&deg[dst[e]], 1);
}

__global__ void k_scan1(const int* __restrict__ deg, int* __restrict__ tmp,
                        int* __restrict__ part, int N) {
    __shared__ int s[SCAN_BS];
    int i = blockIdx.x * SCAN_BS + threadIdx.x;
    int v = (i < N) ? deg[i] : 0;
    s[threadIdx.x] = v;
    __syncthreads();
    for (int off = 1; off < SCAN_BS; off <<= 1) {
        int add = (threadIdx.x >= off) ? s[threadIdx.x - off] : 0;
        __syncthreads();
        s[threadIdx.x] += add;
        __syncthreads();
    }
    if (i < N) tmp[i] = s[threadIdx.x];                 // inclusive
    if (threadIdx.x == SCAN_BS - 1) part[blockIdx.x] = s[threadIdx.x];
}

__global__ void k_scan2(int* __restrict__ part, int nb) {
    if (threadIdx.x != 0 || blockIdx.x != 0) return;
    int run = 0;
    for (int b = 0; b < nb; b++) { int v = part[b]; part[b] = run; run += v; }
}

__global__ void k_scan3(const int* __restrict__ tmp, const int* __restrict__ deg,
                        const int* __restrict__ part,
                        int* __restrict__ rp, int* __restrict__ cur, int N, int E) {
    int i = blockIdx.x * blockDim.x + threadIdx.x;
    if (i < N) {
        int excl = tmp[i] - deg[i] + part[i / SCAN_BS];
        rp[i] = excl;
        cur[i] = excl;
    }
    if (i == 0) rp[N] = E;
}

__global__ void k_fill(const int* __restrict__ src, const int* __restrict__ dst,
                       const float* __restrict__ ew,
                       int* __restrict__ cur, int2* __restrict__ csr, int E) {
    int e = blockIdx.x * blockDim.x + threadIdx.x;
    if (e >= E) return;
    int d = dst[e];
    int pos = atomicAdd(&cur[d], 1);
    csr[pos] = make_int2(src[e], __float_as_int(ew[e]));
}

// ---------------------------------------------------------------------------
// fp16 pull aggregation: thread = (node, 8-half group). One 16B lane-access
// fetches EIGHT features. T = SH/8 threads/node. fp32 accumulation.
// 2-edge unroll with dual accumulators (R3-proven loop shape).
// ---------------------------------------------------------------------------
template <int SH>   // stride in halves (multiple of 8)
__global__ void k_pullh(const __half* __restrict__ h, const int2* __restrict__ csr,
                        const int* __restrict__ rp, float* __restrict__ agg, int N) {
    constexpr int T = SH / 8;
    int t = blockIdx.x * blockDim.x + threadIdx.x;
    int node = t / T;
    int g = t % T;
    if (node >= N) return;
    int e = __ldg(&rp[node]);
    int end = __ldg(&rp[node + 1]);
    const __half* hp = h + g * 8;
    float a[8] = {0, 0, 0, 0, 0, 0, 0, 0};
    float c[8] = {0, 0, 0, 0, 0, 0, 0, 0};
    for (; e + 1 < end; e += 2) {
        int2 p0 = __ldg(&csr[e]);
        int2 p1 = __ldg(&csr[e + 1]);
        float w0 = __int_as_float(p0.y);
        float w1 = __int_as_float(p1.y);
        uint4 v0 = __ldg(reinterpret_cast<const uint4*>(hp + (size_t)p0.x * SH));
        uint4 v1 = __ldg(reinterpret_cast<const uint4*>(hp + (size_t)p1.x * SH));
        const __half2* q0 = reinterpret_cast<const __half2*>(&v0);
        const __half2* q1 = reinterpret_cast<const __half2*>(&v1);
#pragma unroll
        for (int k = 0; k < 4; k++) {
            float2 f0 = __half22float2(q0[k]);
            float2 f1 = __half22float2(q1[k]);
            a[2 * k + 0] += f0.x * w0; a[2 * k + 1] += f0.y * w0;
            c[2 * k + 0] += f1.x * w1; c[2 * k + 1] += f1.y * w1;
        }
    }
    if (e < end) {
        int2 p0 = __ldg(&csr[e]);
        float w0 = __int_as_float(p0.y);
        uint4 v0 = __ldg(reinterpret_cast<const uint4*>(hp + (size_t)p0.x * SH));
        const __half2* q0 = reinterpret_cast<const __half2*>(&v0);
#pragma unroll
        for (int k = 0; k < 4; k++) {
            float2 f0 = __half22float2(q0[k]);
            a[2 * k + 0] += f0.x * w0; a[2 * k + 1] += f0.y * w0;
        }
    }
    float4* o = reinterpret_cast<float4*>(agg + (size_t)node * SH + g * 8);
    o[0] = make_float4(a[0] + c[0], a[1] + c[1], a[2] + c[2], a[3] + c[3]);
    o[1] = make_float4(a[4] + c[4], a[5] + c[5], a[6] + c[6], a[7] + c[7]);
}

// ---------------------------------------------------------------------------
// Node transform: out(half) = act(in @ W (+b)); pads zeroed.
// TIN = float (fp32 agg) or __half (fp16 features for layer-4 pre-transform).
// ---------------------------------------------------------------------------
template <int IN, int INS, int OUT, int OUTS, bool BIAS, bool ACT, typename TIN>
__global__ void k_transform(const TIN* __restrict__ in,
                            const float* __restrict__ W, const float* __restrict__ b,
                            __half* __restrict__ out, int N) {
    __shared__ float sW[IN * OUT];
    __shared__ float sb[OUT > 0 ? OUT : 1];
    for (int i = threadIdx.x; i < IN * OUT; i += blockDim.x) sW[i] = W[i];
    if (BIAS)
        for (int i = threadIdx.x; i < OUT; i += blockDim.x) sb[i] = b[i];
    __syncthreads();
    int n = blockIdx.x * blockDim.x + threadIdx.x;
    if (n >= N) return;
    float a[IN];
#pragma unroll
    for (int k = 0; k < IN; k++) a[k] = (float)in[(size_t)n * INS + k];
    __half* orow = out + (size_t)n * OUTS;
    for (int of = 0; of < OUT; of++) {
        float acc = BIAS ? sb[of] : 0.0f;
#pragma unroll
        for (int k = 0; k < IN; k++) acc += a[k] * sW[k * OUT + of];
        if (ACT) acc = lrelu(acc);
        orow[of] = __float2half(acc);
    }
    for (int of = OUT; of < OUTS; of++) orow[of] = __float2half(0.0f);
}

// ---------------------------------------------------------------------------
// Pool with fused layer-4 bias + double lrelu. h fp32 stride 56, cols<50.
// batch sorted -> run-length local accumulation, atomics on boundaries only.
// ---------------------------------------------------------------------------
__global__ void k_pool(const float* __restrict__ h, const int* __restrict__ batch,
                       const float* __restrict__ b4,
                       float* __restrict__ pooled, int N) {
    int g = blockIdx.y;                                   // 0..12 feature group
    int c0 = g * 4;
    float bx = (c0 + 0 < 50) ? b4[c0 + 0] : 0.f;
    float by = (c0 + 1 < 50) ? b4[c0 + 1] : 0.f;
    float bz = (c0 + 2 < 50) ? b4[c0 + 2] : 0.f;
    float bw = (c0 + 3 < 50) ? b4[c0 + 3] : 0.f;
    int chunk = blockIdx.x * blockDim.x + threadIdx.x;
    int n0 = chunk * 64;
    if (n0 >= N) return;
    int n1 = min(n0 + 64, N);
    int cur = batch[n0];
    float4 acc = make_float4(0.f, 0.f, 0.f, 0.f);
    for (int n = n0; n < n1; n++) {
        int bg = batch[n];
        if (bg != cur) {
            atomicAdd(reinterpret_cast<float4*>(pooled + (size_t)cur * 52 + c0), acc);
            acc = make_float4(0.f, 0.f, 0.f, 0.f);
            cur = bg;
        }
        float4 v = *reinterpret_cast<const float4*>(h + (size_t)n * 56 + c0);
        if (c0 + 0 < 50) acc.x += lrelu(lrelu(v.x + bx));
        if (c0 + 1 < 50) acc.y += lrelu(lrelu(v.y + by));
        if (c0 + 2 < 50) acc.z += lrelu(lrelu(v.z + bz));
        if (c0 + 3 < 50) acc.w += lrelu(lrelu(v.w + bw));
    }
    atomicAdd(reinterpret_cast<float4*>(pooled + (size_t)cur * 52 + c0), acc);
}

// ---------------------------------------------------------------------------
// Zero fill (float4)
// ---------------------------------------------------------------------------
__global__ void k_zero(float4* __restrict__ p, int n4) {
    int i = blockIdx.x * blockDim.x + threadIdx.x;
    if (i < n4) p[i] = make_float4(0.f, 0.f, 0.f, 0.f);
}

// ---------------------------------------------------------------------------
// MLP head: [G,50] -> 30 -> 20 -> 2
// ---------------------------------------------------------------------------
__global__ void k_fc(const float* __restrict__ pooled,
                     const float* __restrict__ W1, const float* __restrict__ b1,
                     const float* __restrict__ W2, const float* __restrict__ b2,
                     const float* __restrict__ W3, const float* __restrict__ b3,
                     float* __restrict__ out) {
    __shared__ float s1[50 * 30], s2[30 * 20], s3[20 * 2];
    __shared__ float t1[30], t2[20], t3[2];
    for (int i = threadIdx.x; i < 50 * 30; i += blockDim.x) s1[i] = W1[i];
    for (int i = threadIdx.x; i < 30 * 20; i += blockDim.x) s2[i] = W2[i];
    for (int i = threadIdx.x; i < 20 * 2; i += blockDim.x) s3[i] = W3[i];
    if (threadIdx.x < 30) t1[threadIdx.x] = b1[threadIdx.x];
    if (threadIdx.x < 20) t2[threadIdx.x] = b2[threadIdx.x];
    if (threadIdx.x < 2) t3[threadIdx.x] = b3[threadIdx.x];
    __syncthreads();
    int gi = blockIdx.x * blockDim.x + threadIdx.x;
    if (gi >= NG) return;
    float p[50];
#pragma unroll
    for (int k = 0; k < 50; k++) p[k] = pooled[(size_t)gi * 52 + k];
    float a1[30];
    for (int of = 0; of < 30; of++) {
        float acc = t1[of];
#pragma unroll
        for (int k = 0; k < 50; k++) acc += p[k] * s1[k * 30 + of];
        a1[of] = lrelu(acc);
    }
    float a2[20];
    for (int of = 0; of < 20; of++) {
        float acc = t2[of];
#pragma unroll
        for (int k = 0; k < 30; k++) acc += a1[k] * s2[k * 20 + of];
        a2[of] = lrelu(acc);
    }
#pragma unroll
    for (int of = 0; of < 2; of++) {
        float acc = t3[of];
#pragma unroll
        for (int k = 0; k < 20; k++) acc += a2[k] * s3[k * 2 + of];
        out[(size_t)gi * 2 + of] = lrelu(acc);
    }
}

// ---------------------------------------------------------------------------
extern "C" void kernel_launch(void* const* d_in, const int* in_sizes, int n_in,
                              void* d_out, int out_size) {
    const float* x     = (const float*)d_in[0];
    const void*  ei    = d_in[1];
    const float* ew    = (const float*)d_in[2];
    const void*  batch = d_in[3];
    const float* W1 = (const float*)d_in[4];  const float* b1 = (const float*)d_in[5];
    const float* W2 = (const float*)d_in[6];  const float* b2 = (const float*)d_in[7];
    const float* W3 = (const float*)d_in[8];  const float* b3 = (const float*)d_in[9];
    const float* W4 = (const float*)d_in[10]; const float* b4 = (const float*)d_in[11];
    const float* Wf1 = (const float*)d_in[12]; const float* bf1 = (const float*)d_in[13];
    const float* Wf2 = (const float*)d_in[14]; const float* bf2 = (const float*)d_in[15];
    const float* Wf3 = (const float*)d_in[16]; const float* bf3 = (const float*)d_in[17];
    float* out = (float*)d_out;

    int N = in_sizes[0] / 6;
    int E = in_sizes[2];

    float *bufA, *bufB, *pool;
    __half* h16;
    int *src, *dst, *batch32, *deg, *tmp, *rp, *cur, *part;
    int2* csr;
    cudaGetSymbolAddress((void**)&bufA, g_bufA);
    cudaGetSymbolAddress((void**)&bufB, g_bufB);
    cudaGetSymbolAddress((void**)&h16, g_h16);
    cudaGetSymbolAddress((void**)&pool, g_pool);
    cudaGetSymbolAddress((void**)&src, g_src);
    cudaGetSymbolAddress((void**)&dst, g_dst);
    cudaGetSymbolAddress((void**)&batch32, g_batch);
    cudaGetSymbolAddress((void**)&deg, g_deg);
    cudaGetSymbolAddress((void**)&tmp, g_tmp);
    cudaGetSymbolAddress((void**)&rp, g_rp);
    cudaGetSymbolAddress((void**)&cur, g_cur);
    cudaGetSymbolAddress((void**)&part, g_part);
    cudaGetSymbolAddress((void**)&csr, g_csr);

    const int BT = 256;
    int nb = (N + SCAN_BS - 1) / SCAN_BS;

    k_detect<<<1, 32>>>((const int*)ei, (const int*)batch, E, N);
    int mx = E > N ? E : N;
    k_prep<<<(mx + BT - 1) / BT, BT>>>(ei, batch, x, src, dst, batch32, deg, h16, N, E);

    // CSR build
    k_hist<<<(E + BT - 1) / BT, BT>>>(dst, deg, E);
    k_scan1<<<nb, SCAN_BS>>>(deg, tmp, part, N);
    k_scan2<<<1, 32>>>(part, nb);
    k_scan3<<<(N + BT - 1) / BT, BT>>>(tmp, deg, part, rp, cur, N, E);
    k_fill<<<(E + BT - 1) / BT, BT>>>(src, dst, ew, cur, csr, E);

    // ---- Layer 1: pull fp16 dim8 (T=1), transform 6->16 (h16)
    k_pullh<8><<<(N + BT - 1) / BT, BT>>>(h16, csr, rp, bufA, N);
    k_transform<6, 8, 16, 16, true, true, float><<<(N + 127) / 128, 128>>>(bufA, W1, b1, h16, N);
    // ---- Layer 2: pull fp16 dim16 (T=2), transform 16->32
    k_pullh<16><<<((N * 2) + BT - 1) / BT, BT>>>(h16, csr, rp, bufA, N);
    k_transform<16, 16, 32, 32, true, true, float><<<(N + 127) / 128, 128>>>(bufA, W2, b2, h16, N);
    // ---- Layer 3: pull fp16 dim32 (T=4), transform 32->64
    k_pullh<32><<<((N * 4) + BT - 1) / BT, BT>>>(h16, csr, rp, bufA, N);
    k_transform<32, 32, 64, 64, true, true, float><<<(N + 127) / 128, 128>>>(bufA, W3, b3, h16, N);
    // ---- Layer 4: pre-transform 64->50 (fp16 in, pad 56), pull fp16 dim56 (T=7)
    {
        __half* t4 = reinterpret_cast<__half*>(bufB);     // reuse bufB as fp16 scratch
        k_transform<64, 64, 50, 56, false, false, __half><<<(N + 127) / 128, 128>>>(h16, W4, nullptr, t4, N);
        k_pullh<56><<<(unsigned)(((long long)N * 7 + BT - 1) / BT), BT>>>(t4, csr, rp, bufA, N);
    }

    // ---- Pool (fused bias + double lrelu), reads fp32 stride 56
    {
        int n4 = NG * 52 / 4;
        k_zero<<<(n4 + BT - 1) / BT, BT>>>((float4*)pool, n4);
        int chunks = (N + 63) / 64;
        dim3 grid((chunks + 127) / 128, 13);
        k_pool<<<grid, 128>>>(bufA, batch32, b4, pool, N);
    }
    // ---- MLP head
    k_fc<<<(NG + BT - 1) / BT, BT>>>(pool, Wf1, bf1, Wf2, bf2, Wf3, bf3, out);
}